// round 8
// baseline (speedup 1.0000x reference)
#include <cuda_runtime.h>
#include <cstdint>

#define D 50
#define H1 17
#define H3 10
#define WARPS_PER_BLOCK 4

// Precomputed collapsed-linear operators (written by precompute_kernel)
__device__ float g_v[D];        // atte.sum(axis=1)
__device__ float g_u2[D];       // W1 @ W2            -> logits direction
__device__ float g_U4[D * 2];   // W1 @ W3 @ W4       -> h2 directions
__device__ float g_c[3];        // [b1@W2+b2, ((b1@W3+b3)@W4+b4)[0..1]]

// Parallel fp32 precompute: 1 block x 1024 threads.
__global__ __launch_bounds__(1024) void precompute_kernel(
    const float* __restrict__ atte,
    const float* __restrict__ W1, const float* __restrict__ b1,
    const float* __restrict__ W2, const float* __restrict__ b2,
    const float* __restrict__ W3, const float* __restrict__ b3,
    const float* __restrict__ W4, const float* __restrict__ b4) {
    int tid = threadIdx.x;
    int warp = tid >> 5, lane = tid & 31;

    {
        int d = warp;
        const float* row = atte + d * D;
        float a = row[lane] + ((lane < D - 32) ? row[32 + lane] : 0.0f);
#pragma unroll
        for (int o = 16; o; o >>= 1) a += __shfl_xor_sync(0xFFFFFFFFu, a, o);
        if (lane == 0) g_v[d] = a;
    }
    if (warp < D - 32) {
        int d = 32 + warp;
        const float* row = atte + d * D;
        float a = row[lane] + ((lane < D - 32) ? row[32 + lane] : 0.0f);
#pragma unroll
        for (int o = 16; o; o >>= 1) a += __shfl_xor_sync(0xFFFFFFFFu, a, o);
        if (lane == 0) g_v[d] = a;
    }

    int d = tid;
    if (d < D) {
        float u2 = 0.f;
#pragma unroll
        for (int j = 0; j < H1; ++j) u2 = fmaf(W1[d * H1 + j], W2[j], u2);
        g_u2[d] = u2;

        float m[H3];
#pragma unroll
        for (int t = 0; t < H3; ++t) {
            float a = 0.f;
#pragma unroll
            for (int j = 0; j < H1; ++j) a = fmaf(W1[d * H1 + j], W3[j * H3 + t], a);
            m[t] = a;
        }
#pragma unroll
        for (int p = 0; p < 2; ++p) {
            float a = 0.f;
#pragma unroll
            for (int t = 0; t < H3; ++t) a = fmaf(m[t], W4[t * 2 + p], a);
            g_U4[d * 2 + p] = a;
        }
    }
    if (d == D) {
        float c2 = b2[0];
#pragma unroll
        for (int j = 0; j < H1; ++j) c2 = fmaf(b1[j], W2[j], c2);
        g_c[0] = c2;
        float t[H3];
#pragma unroll
        for (int m = 0; m < H3; ++m) {
            float a = b3[m];
#pragma unroll
            for (int j = 0; j < H1; ++j) a = fmaf(b1[j], W3[j * H3 + m], a);
            t[m] = a;
        }
#pragma unroll
        for (int p = 0; p < 2; ++p) {
            float a = b4[p];
#pragma unroll
            for (int m = 0; m < H3; ++m) a = fmaf(t[m], W4[m * 2 + p], a);
            g_c[1 + p] = a;
        }
    }
}

// rootid may be int32 (JAX x64 disabled) or int64. Detect via sentinel check.
__device__ __forceinline__ long long load_root(const void* p, int i, bool is32) {
    if (is32) return (long long)((const int*)p)[i];
    return ((const long long*)p)[i];
}

__device__ __forceinline__ uint32_t smem_addr_u32(const void* p) {
    return (uint32_t)__cvta_generic_to_shared(p);
}

// ============================================================================
// FAST PATH (ROWS in (16,32]): zero smem. Coalesced LDG partials + register-
// halving butterfly puts score of row i on lane i. Top-k rows re-read from L1.
// ============================================================================
template <int ROWS>
__global__ __launch_bounds__(32 * WARPS_PER_BLOCK, 8) void session_kernel_ldg(
    const float* __restrict__ emd,
    const void* __restrict__ rootid,
    const int* __restrict__ kptr,
    float* __restrict__ out,
    int S, int Nspans) {
    static_assert(ROWS > 16 && ROWS <= 32, "fast path expects 16<ROWS<=32");
    int tid = threadIdx.x;
    int warp = tid >> 5, lane = tid & 31;
    int s = blockIdx.x * WARPS_PER_BLOCK + warp;
    if (s >= S) return;

    bool is32 = (((const int*)rootid)[S - 1] == Nspans);
    long long start = (s == 0) ? 0LL : load_root(rootid, s - 1, is32);
    long long end = load_root(rootid, s, is32);
    int len = (int)(end - start);
    if (len > ROWS) len = ROWS;
    if (len < 0) len = 0;
    int k = *kptr;
    if (k > len) k = len;
    if (k < 0) k = 0;

    const float* base = emd + (size_t)start * D;
    bool hi_ok = (lane < D - 32);
    float v0 = g_v[lane];
    float v1 = hi_ok ? g_v[lane + 32] : 0.0f;

    // ---- per-row partials: 2 coalesced LDGs per row, all independent ----
    float p[ROWS];
#pragma unroll
    for (int i = 0; i < ROWS; ++i) {
        if (i < len) {
            float x0 = __ldg(base + i * D + lane);
            float x1 = hi_ok ? __ldg(base + i * D + 32 + lane) : 0.0f;
            p[i] = fmaf(x0, v0, x1 * v1);
        } else {
            p[i] = 0.0f;
        }
    }

    // ---- register-halving butterfly: lane i ends with score of row i ----
    // Round off=16 specialized: slots ROWS..31 are implicit zeros.
    {
        bool hi = (lane & 16) != 0;
#pragma unroll
        for (int j = 0; j < 16; ++j) {
            float q = (j + 16 < ROWS) ? p[j + 16] : 0.0f;
            float a = hi ? q : p[j];
            float b = hi ? p[j] : q;
            p[j] = a + __shfl_xor_sync(0xFFFFFFFFu, b, 16);
        }
    }
#pragma unroll
    for (int off = 8; off >= 1; off >>= 1) {
        bool hi = (lane & off) != 0;
#pragma unroll
        for (int j = 0; j < off; ++j) {
            float a = hi ? p[j + off] : p[j];
            float b = hi ? p[j] : p[j + off];
            p[j] = a + __shfl_xor_sync(0xFFFFFFFFu, b, off);
        }
    }
    float score = p[0];

    // ---- top-k selection, tie -> lowest row index (stable-sort semantics) ----
    unsigned key;
    {
        unsigned ub = __float_as_uint(score);
        key = (ub & 0x80000000u) ? ~ub : (ub | 0x80000000u);  // order-preserving map
    }
    unsigned cand = (len >= 32) ? 0xFFFFFFFFu : ((1u << len) - 1u);
    unsigned sel = 0u;
    for (int r = 0; r < k; ++r) {
        unsigned mykey = ((cand >> lane) & 1u) ? key : 0u;
        unsigned mx = __reduce_max_sync(0xFFFFFFFFu, mykey);
        unsigned winners = __ballot_sync(0xFFFFFFFFu,
                                         (mykey == mx) && ((cand >> lane) & 1u));
        if (winners == 0u) break;
        int w = __ffs(winners) - 1;
        sel |= 1u << w;
        cand &= ~(1u << w);
    }

    // ---- sum selected rows (re-read; L1-hot: this warp just streamed them) ----
    float a0 = 0.f, a1 = 0.f;
    unsigned m = sel;
    while (m) {
        int i = __ffs(m) - 1;
        m &= m - 1;
        a0 += __ldg(base + i * D + lane);
        if (hi_ok) a1 += __ldg(base + i * D + 32 + lane);
    }

    // ---- collapsed linear head: 3 dots over 50 dims ----
    float pl = a0 * g_u2[lane];
    float p0 = a0 * g_U4[lane * 2 + 0];
    float p1 = a0 * g_U4[lane * 2 + 1];
    if (hi_ok) {
        pl = fmaf(a1, g_u2[lane + 32], pl);
        p0 = fmaf(a1, g_U4[(lane + 32) * 2 + 0], p0);
        p1 = fmaf(a1, g_U4[(lane + 32) * 2 + 1], p1);
    }
#pragma unroll
    for (int o = 16; o; o >>= 1) {
        pl += __shfl_xor_sync(0xFFFFFFFFu, pl, o);
        p0 += __shfl_xor_sync(0xFFFFFFFFu, p0, o);
        p1 += __shfl_xor_sync(0xFFFFFFFFu, p1, o);
    }
    if (lane == 0) {
        out[s] = pl + g_c[0];                // logits [S,1]
        out[S + 2 * s + 0] = p0 + g_c[1];    // h2 [S,2]
        out[S + 2 * s + 1] = p1 + g_c[2];
    }
}

// ============================================================================
// GENERIC FALLBACK: R6 winner (cp.async smem staging), for L outside fast path
// ============================================================================
extern __shared__ float s_dyn[];

__global__ __launch_bounds__(32 * WARPS_PER_BLOCK) void session_kernel_smem(
    const float* __restrict__ emd,
    const void* __restrict__ rootid,
    const int* __restrict__ kptr,
    float* __restrict__ out,
    int S, int Nspans, int L) {
    float* sv = s_dyn;
    int tid = threadIdx.x;
    if (tid < D) sv[tid] = g_v[tid];
    __syncthreads();

    int warp = tid >> 5, lane = tid & 31;
    int s = blockIdx.x * WARPS_PER_BLOCK + warp;
    if (s >= S) return;

    float* srow = s_dyn + 64 + warp * (L * D);

    bool is32 = (((const int*)rootid)[S - 1] == Nspans);
    long long start = (s == 0) ? 0LL : load_root(rootid, s - 1, is32);
    long long end = load_root(rootid, s, is32);
    int len = (int)(end - start);
    if (len > L) len = L;
    if (len > 32) len = 32;
    if (len < 0) len = 0;
    int k = *kptr;
    if (k > len) k = len;
    if (k < 0) k = 0;

    size_t baseElem = (size_t)start * D;
    const float* src = emd + baseElem;
    int nW = len * D;
    if ((baseElem & 3) == 0) {
        int n16 = nW >> 2;
        uint32_t dbase = smem_addr_u32(srow);
#pragma unroll 4
        for (int t = lane; t < n16; t += 32) {
            const float* g = src + t * 4;
            asm volatile("cp.async.cg.shared.global [%0], [%1], 16;"
                         :: "r"(dbase + t * 16), "l"(g));
        }
        for (int t = (n16 << 2) + lane; t < nW; t += 32) srow[t] = __ldg(src + t);
        asm volatile("cp.async.commit_group;");
        asm volatile("cp.async.wait_group 0;");
    } else {
#pragma unroll 4
        for (int t = lane; t < nW; t += 32) srow[t] = __ldg(src + t);
    }
    __syncwarp();

    float score = 0.0f;
    if (lane < len) {
        const float2* row = (const float2*)&srow[lane * D];
        const float2* vv = (const float2*)sv;
        float s0 = 0.f, s1 = 0.f, s2 = 0.f, s3 = 0.f;
#pragma unroll
        for (int j = 0; j < 24; j += 4) {
            float2 r0 = row[j], r1 = row[j + 1], r2 = row[j + 2], r3 = row[j + 3];
            float2 w0 = vv[j], w1 = vv[j + 1], w2 = vv[j + 2], w3 = vv[j + 3];
            s0 = fmaf(r0.x, w0.x, s0); s0 = fmaf(r0.y, w0.y, s0);
            s1 = fmaf(r1.x, w1.x, s1); s1 = fmaf(r1.y, w1.y, s1);
            s2 = fmaf(r2.x, w2.x, s2); s2 = fmaf(r2.y, w2.y, s2);
            s3 = fmaf(r3.x, w3.x, s3); s3 = fmaf(r3.y, w3.y, s3);
        }
        {
            float2 r = row[24], w = vv[24];
            s0 = fmaf(r.x, w.x, s0); s0 = fmaf(r.y, w.y, s0);
        }
        score = (s0 + s1) + (s2 + s3);
    }

    unsigned key;
    {
        unsigned ub = __float_as_uint(score);
        key = (ub & 0x80000000u) ? ~ub : (ub | 0x80000000u);
    }
    unsigned cand = (len >= 32) ? 0xFFFFFFFFu : ((1u << len) - 1u);
    unsigned sel = 0u;
    for (int r = 0; r < k; ++r) {
        unsigned mykey = ((cand >> lane) & 1u) ? key : 0u;
        unsigned mx = __reduce_max_sync(0xFFFFFFFFu, mykey);
        unsigned winners = __ballot_sync(0xFFFFFFFFu,
                                         (mykey == mx) && ((cand >> lane) & 1u));
        if (winners == 0u) break;
        int w = __ffs(winners) - 1;
        sel |= 1u << w;
        cand &= ~(1u << w);
    }

    float a0 = 0.f, a1 = 0.f;
    unsigned m = sel;
    bool hi_ok = (lane < D - 32);
    while (m) {
        int i = __ffs(m) - 1;
        m &= m - 1;
        const float* row = &srow[i * D];
        a0 += row[lane];
        if (hi_ok) a1 += row[lane + 32];
    }

    float pl = a0 * g_u2[lane];
    float p0 = a0 * g_U4[lane * 2 + 0];
    float p1 = a0 * g_U4[lane * 2 + 1];
    if (hi_ok) {
        pl = fmaf(a1, g_u2[lane + 32], pl);
        p0 = fmaf(a1, g_U4[(lane + 32) * 2 + 0], p0);
        p1 = fmaf(a1, g_U4[(lane + 32) * 2 + 1], p1);
    }
#pragma unroll
    for (int o = 16; o; o >>= 1) {
        pl += __shfl_xor_sync(0xFFFFFFFFu, pl, o);
        p0 += __shfl_xor_sync(0xFFFFFFFFu, p0, o);
        p1 += __shfl_xor_sync(0xFFFFFFFFu, p1, o);
    }
    if (lane == 0) {
        out[s] = pl + g_c[0];
        out[S + 2 * s + 0] = p0 + g_c[1];
        out[S + 2 * s + 1] = p1 + g_c[2];
    }
}

extern "C" void kernel_launch(void* const* d_in, const int* in_sizes, int n_in,
                              void* d_out, int out_size) {
    const float* emd = (const float*)d_in[0];
    const void* rootid = d_in[1];
    const float* atte = (const float*)d_in[2];
    const float* W1 = (const float*)d_in[3];
    const float* b1 = (const float*)d_in[4];
    const float* W2 = (const float*)d_in[5];
    const float* b2 = (const float*)d_in[6];
    const float* W3 = (const float*)d_in[7];
    const float* b3 = (const float*)d_in[8];
    const float* W4 = (const float*)d_in[9];
    const float* b4 = (const float*)d_in[10];
    const int* kptr = (const int*)d_in[11];
    float* out = (float*)d_out;

    int S = in_sizes[1];
    int Nspans = in_sizes[0] / D;
    int L = Nspans / S;  // uniform session length

    precompute_kernel<<<1, 1024>>>(atte, W1, b1, W2, b2, W3, b3, W4, b4);

    int blocks = (S + WARPS_PER_BLOCK - 1) / WARPS_PER_BLOCK;
    if (L == 20) {
        session_kernel_ldg<20><<<blocks, 32 * WARPS_PER_BLOCK>>>(
            emd, rootid, kptr, out, S, Nspans);
    } else {
        int Lc = L < 1 ? 1 : (L > 32 ? 32 : L);
        size_t dynBytes = (64 + (size_t)WARPS_PER_BLOCK * Lc * D) * sizeof(float);
        session_kernel_smem<<<blocks, 32 * WARPS_PER_BLOCK, dynBytes>>>(
            emd, rootid, kptr, out, S, Nspans, Lc);
    }
}

// round 9
// speedup vs baseline: 2.5176x; 2.5176x over previous
#include <cuda_runtime.h>
#include <cstdint>

#define D 50
#define H1 17
#define H3 10
#define WARPS_PER_BLOCK 4

// Precomputed collapsed-linear operators (written by precompute_kernel)
__device__ float g_v[D];        // atte.sum(axis=1)
__device__ float g_u2[D];       // W1 @ W2            -> logits direction
__device__ float g_U4[D * 2];   // W1 @ W3 @ W4       -> h2 directions
__device__ float g_c[3];        // [b1@W2+b2, ((b1@W3+b3)@W4+b4)[0..1]]

// Parallel fp32 precompute: 1 block x 1024 threads.
__global__ __launch_bounds__(1024) void precompute_kernel(
    const float* __restrict__ atte,
    const float* __restrict__ W1, const float* __restrict__ b1,
    const float* __restrict__ W2, const float* __restrict__ b2,
    const float* __restrict__ W3, const float* __restrict__ b3,
    const float* __restrict__ W4, const float* __restrict__ b4) {
    int tid = threadIdx.x;
    int warp = tid >> 5, lane = tid & 31;

    {
        int d = warp;
        const float* row = atte + d * D;
        float a = row[lane] + ((lane < D - 32) ? row[32 + lane] : 0.0f);
#pragma unroll
        for (int o = 16; o; o >>= 1) a += __shfl_xor_sync(0xFFFFFFFFu, a, o);
        if (lane == 0) g_v[d] = a;
    }
    if (warp < D - 32) {
        int d = 32 + warp;
        const float* row = atte + d * D;
        float a = row[lane] + ((lane < D - 32) ? row[32 + lane] : 0.0f);
#pragma unroll
        for (int o = 16; o; o >>= 1) a += __shfl_xor_sync(0xFFFFFFFFu, a, o);
        if (lane == 0) g_v[d] = a;
    }

    int d = tid;
    if (d < D) {
        float u2 = 0.f;
#pragma unroll
        for (int j = 0; j < H1; ++j) u2 = fmaf(W1[d * H1 + j], W2[j], u2);
        g_u2[d] = u2;

        float m[H3];
#pragma unroll
        for (int t = 0; t < H3; ++t) {
            float a = 0.f;
#pragma unroll
            for (int j = 0; j < H1; ++j) a = fmaf(W1[d * H1 + j], W3[j * H3 + t], a);
            m[t] = a;
        }
#pragma unroll
        for (int p = 0; p < 2; ++p) {
            float a = 0.f;
#pragma unroll
            for (int t = 0; t < H3; ++t) a = fmaf(m[t], W4[t * 2 + p], a);
            g_U4[d * 2 + p] = a;
        }
    }
    if (d == D) {
        float c2 = b2[0];
#pragma unroll
        for (int j = 0; j < H1; ++j) c2 = fmaf(b1[j], W2[j], c2);
        g_c[0] = c2;
        float t[H3];
#pragma unroll
        for (int m = 0; m < H3; ++m) {
            float a = b3[m];
#pragma unroll
            for (int j = 0; j < H1; ++j) a = fmaf(b1[j], W3[j * H3 + m], a);
            t[m] = a;
        }
#pragma unroll
        for (int p = 0; p < 2; ++p) {
            float a = b4[p];
#pragma unroll
            for (int m = 0; m < H3; ++m) a = fmaf(t[m], W4[m * 2 + p], a);
            g_c[1 + p] = a;
        }
    }
}

// rootid may be int32 (JAX x64 disabled) or int64. Detect via sentinel check.
__device__ __forceinline__ long long load_root(const void* p, int i, bool is32) {
    if (is32) return (long long)((const int*)p)[i];
    return ((const long long*)p)[i];
}

__device__ __forceinline__ uint32_t smem_addr_u32(const void* p) {
    return (uint32_t)__cvta_generic_to_shared(p);
}

// Dynamic smem layout (16B-aligned sections):
//   [0   .. 256)                 : sv (v vector, 50 floats used)
//   [256 .. 256+8*W)             : per-warp mbarrier (8B each)
//   [288 .. 288 + w*4*L*D .. )   : per-warp session buffer (L*D floats)
extern __shared__ float s_dyn[];

__global__ __launch_bounds__(32 * WARPS_PER_BLOCK) void session_kernel(
    const float* __restrict__ emd,
    const void* __restrict__ rootid,
    const int* __restrict__ kptr,
    float* __restrict__ out,
    int S, int Nspans, int L) {
    float* sv = s_dyn;
    int tid = threadIdx.x;
    if (tid < D) sv[tid] = g_v[tid];

    int warp = tid >> 5, lane = tid & 31;
    uint32_t mbar = smem_addr_u32(s_dyn) + 256 + warp * 8;
    if (lane == 0) {
        asm volatile("mbarrier.init.shared.b64 [%0], 1;" :: "r"(mbar) : "memory");
    }
    __syncthreads();   // sv visible + all mbarriers initialized

    int s = blockIdx.x * WARPS_PER_BLOCK + warp;
    if (s >= S) return;

    float* srow = s_dyn + 72 + warp * (L * D);   // 288 bytes = 72 floats

    bool is32 = (((const int*)rootid)[S - 1] == Nspans);
    long long start = (s == 0) ? 0LL : load_root(rootid, s - 1, is32);
    long long end = load_root(rootid, s, is32);
    int len = (int)(end - start);
    if (len > L) len = L;
    if (len > 32) len = 32;
    if (len < 0) len = 0;
    int k = *kptr;
    if (k > len) k = len;
    if (k < 0) k = 0;

    // ---- stage session rows into smem via ONE bulk copy (UBLKCP) ----
    size_t baseByte = (size_t)start * D * sizeof(float);
    const char* src = (const char*)emd + baseByte;
    unsigned nBytes = (unsigned)(len * D * sizeof(float));
    bool bulk_ok = ((baseByte & 15) == 0);
    unsigned bulkBytes = bulk_ok ? (nBytes & ~15u) : 0u;

    if (lane == 0) {
        if (bulkBytes > 0) {
            asm volatile("mbarrier.arrive.expect_tx.shared.b64 _, [%0], %1;"
                         :: "r"(mbar), "r"(bulkBytes) : "memory");
            asm volatile(
                "cp.async.bulk.shared::cta.global.mbarrier::complete_tx::bytes "
                "[%0], [%1], %2, [%3];"
                :: "r"(smem_addr_u32(srow)), "l"(src), "r"(bulkBytes), "r"(mbar)
                : "memory");
        } else {
            asm volatile("mbarrier.arrive.shared.b64 _, [%0];"
                         :: "r"(mbar) : "memory");
        }
    }
    // tail / unaligned fallback words via plain loads
    for (unsigned t = (bulkBytes >> 2) + lane; t < (nBytes >> 2); t += 32)
        srow[t] = __ldg((const float*)src + t);
    __syncwarp();

    // ---- wait for bulk completion (phase 0) ----
    {
        uint32_t done;
        asm volatile(
            "{\n\t"
            ".reg .pred p;\n\t"
            "mbarrier.try_wait.parity.acquire.cta.shared::cta.b64 p, [%1], 0;\n\t"
            "selp.b32 %0, 1, 0, p;\n\t"
            "}"
            : "=r"(done) : "r"(mbar) : "memory");
        if (!done) {
            asm volatile(
                "{\n\t"
                ".reg .pred P1;\n\t"
                "WAIT_LOOP_%=:\n\t"
                "mbarrier.try_wait.parity.acquire.cta.shared::cta.b64 P1, [%0], 0, 0x989680;\n\t"
                "@P1 bra.uni WAIT_DONE_%=;\n\t"
                "bra.uni WAIT_LOOP_%=;\n\t"
                "WAIT_DONE_%=:\n\t"
                "}"
                :: "r"(mbar) : "memory");
        }
    }

    // ---- per-row score: dot(row, v); lane i = row i; 4 independent chains ----
    float score = 0.0f;
    if (lane < len) {
        const float2* row = (const float2*)&srow[lane * D];
        const float2* vv = (const float2*)sv;
        float s0 = 0.f, s1 = 0.f, s2 = 0.f, s3 = 0.f;
#pragma unroll
        for (int j = 0; j < 24; j += 4) {
            float2 r0 = row[j], r1 = row[j + 1], r2 = row[j + 2], r3 = row[j + 3];
            float2 w0 = vv[j], w1 = vv[j + 1], w2 = vv[j + 2], w3 = vv[j + 3];
            s0 = fmaf(r0.x, w0.x, s0); s0 = fmaf(r0.y, w0.y, s0);
            s1 = fmaf(r1.x, w1.x, s1); s1 = fmaf(r1.y, w1.y, s1);
            s2 = fmaf(r2.x, w2.x, s2); s2 = fmaf(r2.y, w2.y, s2);
            s3 = fmaf(r3.x, w3.x, s3); s3 = fmaf(r3.y, w3.y, s3);
        }
        {
            float2 r = row[24], w = vv[24];
            s0 = fmaf(r.x, w.x, s0); s0 = fmaf(r.y, w.y, s0);
        }
        score = (s0 + s1) + (s2 + s3);
    }

    // ---- top-k selection, tie -> lowest row index (stable-sort semantics) ----
    unsigned key;
    {
        unsigned ub = __float_as_uint(score);
        key = (ub & 0x80000000u) ? ~ub : (ub | 0x80000000u);  // order-preserving map
    }
    unsigned cand = (len >= 32) ? 0xFFFFFFFFu : ((1u << len) - 1u);
    unsigned sel = 0u;
    for (int r = 0; r < k; ++r) {
        unsigned mykey = ((cand >> lane) & 1u) ? key : 0u;
        unsigned mx = __reduce_max_sync(0xFFFFFFFFu, mykey);
        unsigned winners = __ballot_sync(0xFFFFFFFFu,
                                         (mykey == mx) && ((cand >> lane) & 1u));
        if (winners == 0u) break;
        int w = __ffs(winners) - 1;
        sel |= 1u << w;
        cand &= ~(1u << w);
    }

    // ---- sum selected rows; lane j owns dims j and j+32 ----
    float a0 = 0.f, a1 = 0.f;
    unsigned m = sel;
    bool hi_ok = (lane < D - 32);
    while (m) {
        int i = __ffs(m) - 1;
        m &= m - 1;
        const float* row = &srow[i * D];
        a0 += row[lane];                       // conflict-free: consecutive banks
        if (hi_ok) a1 += row[lane + 32];
    }

    // ---- collapsed linear head: 3 dots over 50 dims (weights via L1-hit LDG) ----
    float pl = a0 * g_u2[lane];
    float p0 = a0 * g_U4[lane * 2 + 0];
    float p1 = a0 * g_U4[lane * 2 + 1];
    if (hi_ok) {
        pl = fmaf(a1, g_u2[lane + 32], pl);
        p0 = fmaf(a1, g_U4[(lane + 32) * 2 + 0], p0);
        p1 = fmaf(a1, g_U4[(lane + 32) * 2 + 1], p1);
    }
#pragma unroll
    for (int o = 16; o; o >>= 1) {
        pl += __shfl_xor_sync(0xFFFFFFFFu, pl, o);
        p0 += __shfl_xor_sync(0xFFFFFFFFu, p0, o);
        p1 += __shfl_xor_sync(0xFFFFFFFFu, p1, o);
    }
    if (lane == 0) {
        out[s] = pl + g_c[0];                // logits [S,1]
        out[S + 2 * s + 0] = p0 + g_c[1];    // h2 [S,2]
        out[S + 2 * s + 1] = p1 + g_c[2];
    }
}

extern "C" void kernel_launch(void* const* d_in, const int* in_sizes, int n_in,
                              void* d_out, int out_size) {
    const float* emd = (const float*)d_in[0];
    const void* rootid = d_in[1];
    const float* atte = (const float*)d_in[2];
    const float* W1 = (const float*)d_in[3];
    const float* b1 = (const float*)d_in[4];
    const float* W2 = (const float*)d_in[5];
    const float* b2 = (const float*)d_in[6];
    const float* W3 = (const float*)d_in[7];
    const float* b3 = (const float*)d_in[8];
    const float* W4 = (const float*)d_in[9];
    const float* b4 = (const float*)d_in[10];
    const int* kptr = (const int*)d_in[11];
    float* out = (float*)d_out;

    int S = in_sizes[1];
    int Nspans = in_sizes[0] / D;
    int L = Nspans / S;  // uniform session length
    if (L < 1) L = 1;
    if (L > 32) L = 32;  // lane=row scheme bound (bench: L=20)

    precompute_kernel<<<1, 1024>>>(atte, W1, b1, W2, b2, W3, b3, W4, b4);

    // 288 B header (sv + mbarriers) + per-warp session buffers
    size_t dynBytes = 288 + (size_t)WARPS_PER_BLOCK * L * D * sizeof(float);
    int blocks = (S + WARPS_PER_BLOCK - 1) / WARPS_PER_BLOCK;
    session_kernel<<<blocks, 32 * WARPS_PER_BLOCK, dynBytes>>>(
        emd, rootid, kptr, out, S, Nspans, L);
}